// round 14
// baseline (speedup 1.0000x reference)
#include <cuda_runtime.h>
#include <cuda_bf16.h>
#include <math.h>
#include <stdint.h>

// ---------------- constants ----------------
#define B_ 64
#define S_ 10
#define L_ 30
#define TL_ 15
#define E_ 300
#define KP_ 320          // token-emb K padded to 320 (5 chunks of 64)
#define H_ 256
#define G_ 1024
#define SEN2_ 512
#define NSEN_ 640
#define NR_ 704
#define MPROJ_ (NR_*L_)
#define VOCAB_ 50000

#define LS_KS 264
#define LS_BYTES ((64 + 256) * LS_KS * 2)

// pipelined proj_sen: 128x128 tile, K-chunk 64, stride 72, 2 stages
#define GP_ST 72
#define GP_STAGE (2 * 128 * GP_ST)
#define GP_BYTES (2 * GP_STAGE * 2)

// pipelined proj_doc: 64x128 tile, K-chunk 64, stride 72, 2 stages
#define PDP_ST 72
#define PDP_STAGE ((64 + 128) * PDP_ST)
#define PDP_BYTES (2 * PDP_STAGE * 2)    // 55296 bytes

typedef __nv_bfloat16 bf16;

// ---------------- scratch ----------------
__device__ bf16  g_A[MPROJ_ * KP_];             // gathered token embeddings
__device__ bf16  g_wih_s[2][G_*KP_];
__device__ bf16  g_whh_s[2][G_*H_];
__device__ float g_bias_s[2][G_];
__device__ bf16  g_wih_d[2][G_*SEN2_];
__device__ bf16  g_whh_d[2][G_*H_];
__device__ float g_bias_d[2][G_];
__device__ bf16  g_xw[2][MPROJ_*G_];
__device__ bf16  g_dxw[2][NSEN_*G_];
__device__ bf16  g_h16[2][2][NR_*H_];
__device__ float g_hf[2][NR_*H_];
__device__ bf16  g_dh16[2][2][B_*H_];
__device__ float g_docs[2][B_*S_*H_];
__device__ bf16  g_biased16[NSEN_*SEN2_];

__device__ __forceinline__ float sigm(float x) { return 1.0f / (1.0f + expf(-x)); }

__device__ __forceinline__ void mma16816(float* d, const uint32_t* a, const uint32_t* b) {
    asm volatile(
        "mma.sync.aligned.m16n8k16.row.col.f32.bf16.bf16.f32 "
        "{%0,%1,%2,%3},{%4,%5,%6,%7},{%8,%9},{%0,%1,%2,%3};\n"
        : "+f"(d[0]), "+f"(d[1]), "+f"(d[2]), "+f"(d[3])
        : "r"(a[0]), "r"(a[1]), "r"(a[2]), "r"(a[3]), "r"(b[0]), "r"(b[1]));
}

__device__ __forceinline__ uint32_t smaddr(const void* p) {
    return (uint32_t)__cvta_generic_to_shared(p);
}
__device__ __forceinline__ void cpa(uint32_t d, const void* s, int sz) {
    asm volatile("cp.async.cg.shared.global [%0], [%1], 16, %2;\n"
                 :: "r"(d), "l"(s), "r"(sz));
}
__device__ __forceinline__ void cpa_commit() {
    asm volatile("cp.async.commit_group;\n" ::);
}
template <int N>
__device__ __forceinline__ void cpa_waitg() {
    asm volatile("cp.async.wait_group %0;\n" :: "n"(N));
}
__device__ __forceinline__ void cpa_wait() {
    asm volatile("cp.async.commit_group;\ncp.async.wait_group 0;\n" ::);
}

#define CLUSTER_ARRIVE() asm volatile("barrier.cluster.arrive.aligned;" ::: "memory")
#define CLUSTER_WAIT()   asm volatile("barrier.cluster.wait.aligned;" ::: "memory")

__device__ __forceinline__ uint32_t pack_bf2(float x, float y) {
    __nv_bfloat162 p = __floats2bfloat162_rn(x, y);
    return *(uint32_t*)&p;
}

// ---------------- token gather ----------------
__global__ void gather_tokens(const float* __restrict__ emb,
                              const int* __restrict__ ids,
                              const int* __restrict__ titles) {
    int idx = blockIdx.x * blockDim.x + threadIdx.x;   // one uint4 (8 bf16)
    const int total = MPROJ_ * (KP_ / 8);
    if (idx >= total) return;
    int m = idx / (KP_ / 8), cc = idx % (KP_ / 8);
    int r = m / L_, t = m - r * L_;
    int id;
    if (r < NSEN_) id = ids[r * L_ + t];
    else           id = (t < TL_) ? titles[(r - NSEN_) * TL_ + t] : -1;
    bf16 v[8];
    #pragma unroll
    for (int j = 0; j < 8; ++j) {
        int k = cc * 8 + j;
        float f = (id >= 0 && k < E_) ? emb[(size_t)id * E_ + k] : 0.0f;
        v[j] = __float2bfloat16(f);
    }
    *(uint4*)&g_A[(size_t)m * KP_ + cc * 8] = *(const uint4*)v;
}

// ---------------- weight conversion ----------------
__global__ void conv_sen(const float* __restrict__ wf, const float* __restrict__ bfp,
                         const float* __restrict__ wb, const float* __restrict__ bbp,
                         const float* __restrict__ whf, const float* __restrict__ whb) {
    int idx = blockIdx.x * blockDim.x + threadIdx.x;
    const int T1 = 2 * G_ * KP_;
    const int T2 = 2 * G_ * H_;
    if (idx < T1) {
        int dir = idx / (G_ * KP_);
        int r = (idx / KP_) % G_, k = idx % KP_;
        int u = r >> 2, gate = r & 3, src = gate * H_ + u;
        const float* W = dir ? wb : wf;
        g_wih_s[dir][r * KP_ + k] = __float2bfloat16(k < E_ ? W[(size_t)src * E_ + k] : 0.0f);
    } else if (idx < T1 + T2) {
        int j = idx - T1;
        int dir = j / (G_ * H_);
        int r = (j / H_) % G_, k = j % H_;
        int u = r >> 2, gate = r & 3, src = gate * H_ + u;
        const float* W = dir ? whb : whf;
        g_whh_s[dir][r * H_ + k] = __float2bfloat16(W[(size_t)src * H_ + k]);
    } else if (idx < T1 + T2 + 2 * G_) {
        int j = idx - T1 - T2;
        int dir = j / G_, r = j % G_;
        int u = r >> 2, gate = r & 3;
        g_bias_s[dir][r] = (dir ? bbp : bfp)[gate * H_ + u];
    }
}

__global__ void conv_doc(const float* __restrict__ wf, const float* __restrict__ bfp,
                         const float* __restrict__ wb, const float* __restrict__ bbp,
                         const float* __restrict__ whf, const float* __restrict__ whb) {
    int idx = blockIdx.x * blockDim.x + threadIdx.x;
    const int T1 = 2 * G_ * SEN2_;
    const int T2 = 2 * G_ * H_;
    if (idx < T1) {
        int dir = idx / (G_ * SEN2_);
        int r = (idx / SEN2_) % G_, k = idx % SEN2_;
        int u = r >> 2, gate = r & 3, src = gate * H_ + u;
        const float* W = dir ? wb : wf;
        g_wih_d[dir][r * SEN2_ + k] = __float2bfloat16(W[(size_t)src * SEN2_ + k]);
    } else if (idx < T1 + T2) {
        int j = idx - T1;
        int dir = j / (G_ * H_);
        int r = (j / H_) % G_, k = j % H_;
        int u = r >> 2, gate = r & 3, src = gate * H_ + u;
        const float* W = dir ? whb : whf;
        g_whh_d[dir][r * H_ + k] = __float2bfloat16(W[(size_t)src * H_ + k]);
    } else if (idx < T1 + T2 + 2 * G_) {
        int j = idx - T1 - T2;
        int dir = j / G_, r = j % G_;
        int u = r >> 2, gate = r & 3;
        g_bias_d[dir][r] = (dir ? bbp : bfp)[gate * H_ + u];
    }
}

// ---------------- sentence/title input projection (R10 version) ----------------
__global__ __launch_bounds__(256, 2) void proj_sen16() {
    extern __shared__ bf16 sm[];

    const int dir = blockIdx.z;
    const bf16* __restrict__ W = g_wih_s[dir];
    const float* __restrict__ bias = g_bias_s[dir];
    bf16* __restrict__ out = g_xw[dir];

    const int m0 = blockIdx.y * 128;
    const int n0 = blockIdx.x * 128;
    const int tid = threadIdx.x, lane = tid & 31, warp = tid >> 5;
    const int wm = warp >> 2, wn = warp & 3;
    const int g = lane >> 2, tq = lane & 3;

    auto load_chunk = [&](int c) {
        bf16* As_ = sm + (c & 1) * GP_STAGE;
        bf16* Bs_ = As_ + 128 * GP_ST;
        #pragma unroll
        for (int p = 0; p < 4; ++p) {
            int idx = tid + p * 256;
            int row = idx >> 3, cc = idx & 7;
            cpa(smaddr(&As_[row * GP_ST + cc * 8]),
                &g_A[(size_t)(m0 + row) * KP_ + c * 64 + cc * 8], 16);
            cpa(smaddr(&Bs_[row * GP_ST + cc * 8]),
                &W[(size_t)(n0 + row) * KP_ + c * 64 + cc * 8], 16);
        }
        cpa_commit();
    };

    float acc[4][4][4] = {};

    load_chunk(0);
    #pragma unroll 1
    for (int c = 0; c < KP_ / 64; ++c) {
        if (c + 1 < KP_ / 64) { load_chunk(c + 1); cpa_waitg<1>(); }
        else                  { cpa_waitg<0>(); }
        __syncthreads();

        const bf16* As_ = sm + (c & 1) * GP_STAGE;
        const bf16* Bs_ = As_ + 128 * GP_ST;
        #pragma unroll
        for (int kk = 0; kk < 4; ++kk) {
            const int ko = kk * 16;
            uint32_t a[4][4], b[4][2];
            #pragma unroll
            for (int i = 0; i < 4; ++i) {
                int ar = wm * 64 + i * 16;
                a[i][0] = *(const uint32_t*)&As_[(ar + g) * GP_ST + ko + 2 * tq];
                a[i][1] = *(const uint32_t*)&As_[(ar + g + 8) * GP_ST + ko + 2 * tq];
                a[i][2] = *(const uint32_t*)&As_[(ar + g) * GP_ST + ko + 2 * tq + 8];
                a[i][3] = *(const uint32_t*)&As_[(ar + g + 8) * GP_ST + ko + 2 * tq + 8];
            }
            #pragma unroll
            for (int j = 0; j < 4; ++j) {
                int br = wn * 32 + j * 8 + g;
                b[j][0] = *(const uint32_t*)&Bs_[br * GP_ST + ko + 2 * tq];
                b[j][1] = *(const uint32_t*)&Bs_[br * GP_ST + ko + 2 * tq + 8];
            }
            #pragma unroll
            for (int i = 0; i < 4; ++i)
                #pragma unroll
                for (int j = 0; j < 4; ++j) mma16816(acc[i][j], a[i], b[j]);
        }
        __syncthreads();
    }

    #pragma unroll
    for (int i = 0; i < 4; ++i) {
        #pragma unroll
        for (int j = 0; j < 4; ++j) {
            int mr = wm * 64 + i * 16 + g;
            int n = n0 + wn * 32 + j * 8 + 2 * tq;
            size_t o = (size_t)(m0 + mr) * G_ + n;
            *(uint32_t*)&out[o] =
                pack_bf2(acc[i][j][0] + bias[n], acc[i][j][1] + bias[n + 1]);
            o = (size_t)(m0 + mr + 8) * G_ + n;
            *(uint32_t*)&out[o] =
                pack_bf2(acc[i][j][2] + bias[n], acc[i][j][3] + bias[n + 1]);
        }
    }
}

// ---------------- document input projection (NEW: 2-stage pipelined) ----------------
__global__ __launch_bounds__(256, 2) void proj_doc16() {
    extern __shared__ bf16 sm[];

    const int dir = blockIdx.z;
    const bf16* __restrict__ W = g_wih_d[dir];
    const float* __restrict__ bias = g_bias_d[dir];
    bf16* __restrict__ out = g_dxw[dir];

    const int m0 = blockIdx.y * 64;
    const int n0 = blockIdx.x * 128;
    const int tid = threadIdx.x, lane = tid & 31, warp = tid >> 5;
    const int wm = warp >> 2, wn = warp & 3;
    const int g = lane >> 2, tq = lane & 3;

    // stage: A (64 x PDP_ST) then B (128 x PDP_ST)
    auto load_chunk = [&](int c) {
        bf16* As_ = sm + (c & 1) * PDP_STAGE;
        bf16* Bs_ = As_ + 64 * PDP_ST;
        #pragma unroll
        for (int p = 0; p < 2; ++p) {
            int idx = tid + p * 256;          // 512 = 64 rows x 8 subchunks
            int row = idx >> 3, cc = idx & 7;
            cpa(smaddr(&As_[row * PDP_ST + cc * 8]),
                &g_biased16[(size_t)(m0 + row) * SEN2_ + c * 64 + cc * 8], 16);
        }
        #pragma unroll
        for (int p = 0; p < 4; ++p) {
            int idx = tid + p * 256;          // 1024 = 128 rows x 8 subchunks
            int row = idx >> 3, cc = idx & 7;
            cpa(smaddr(&Bs_[row * PDP_ST + cc * 8]),
                &W[(size_t)(n0 + row) * SEN2_ + c * 64 + cc * 8], 16);
        }
        cpa_commit();
    };

    float acc[2][4][4] = {};

    load_chunk(0);
    #pragma unroll 1
    for (int c = 0; c < SEN2_ / 64; ++c) {
        if (c + 1 < SEN2_ / 64) { load_chunk(c + 1); cpa_waitg<1>(); }
        else                    { cpa_waitg<0>(); }
        __syncthreads();

        const bf16* As_ = sm + (c & 1) * PDP_STAGE;
        const bf16* Bs_ = As_ + 64 * PDP_ST;
        #pragma unroll
        for (int kk = 0; kk < 4; ++kk) {
            const int ko = kk * 16;
            uint32_t a[2][4], b[4][2];
            #pragma unroll
            for (int i = 0; i < 2; ++i) {
                int ar = wm * 32 + i * 16;
                a[i][0] = *(const uint32_t*)&As_[(ar + g) * PDP_ST + ko + 2 * tq];
                a[i][1] = *(const uint32_t*)&As_[(ar + g + 8) * PDP_ST + ko + 2 * tq];
                a[i][2] = *(const uint32_t*)&As_[(ar + g) * PDP_ST + ko + 2 * tq + 8];
                a[i][3] = *(const uint32_t*)&As_[(ar + g + 8) * PDP_ST + ko + 2 * tq + 8];
            }
            #pragma unroll
            for (int j = 0; j < 4; ++j) {
                int br = wn * 32 + j * 8 + g;
                b[j][0] = *(const uint32_t*)&Bs_[br * PDP_ST + ko + 2 * tq];
                b[j][1] = *(const uint32_t*)&Bs_[br * PDP_ST + ko + 2 * tq + 8];
            }
            #pragma unroll
            for (int i = 0; i < 2; ++i)
                #pragma unroll
                for (int j = 0; j < 4; ++j) mma16816(acc[i][j], a[i], b[j]);
        }
        __syncthreads();
    }

    #pragma unroll
    for (int i = 0; i < 2; ++i) {
        #pragma unroll
        for (int j = 0; j < 4; ++j) {
            int mr = wm * 32 + i * 16 + g;
            int n = n0 + wn * 32 + j * 8 + 2 * tq;
            size_t o = (size_t)(m0 + mr) * G_ + n;
            *(uint32_t*)&out[o] =
                pack_bf2(acc[i][j][0] + bias[n], acc[i][j][1] + bias[n + 1]);
            o = (size_t)(m0 + mr + 8) * G_ + n;
            *(uint32_t*)&out[o] =
                pack_bf2(acc[i][j][2] + bias[n], acc[i][j][3] + bias[n + 1]);
        }
    }
}

// ---------------- cluster-persistent LSTM (R10 version) ----------------
template <int MODE>
__global__ __launch_bounds__(256, 1) __cluster_dims__(4, 1, 1)
void lstm_cluster() {
    extern __shared__ bf16 sm[];
    bf16* Bs = sm;
    bf16* As = sm + 256 * LS_KS;

    const int dir = blockIdx.z;
    const bf16* __restrict__ Wh = (MODE == 0) ? g_whh_s[dir] : g_whh_d[dir];
    const bf16* __restrict__ xw = (MODE == 0) ? g_xw[dir] : g_dxw[dir];
    float* __restrict__ hf = (MODE == 0) ? g_hf[dir] : nullptr;
    float* __restrict__ docs = (MODE == 1) ? g_docs[dir] : nullptr;

    const int m0 = blockIdx.y * 64;
    const int n0 = blockIdx.x * 256;
    const int tlen = (MODE == 0) ? ((m0 < NSEN_) ? L_ : TL_) : S_;
    const int TMAIN = (MODE == 0) ? L_ : S_;

    const int tid = threadIdx.x, lane = tid & 31, warp = tid >> 5;
    const int wm = warp >> 2, wn = warp & 3;
    const int g = lane >> 2, tq = lane & 3;

    for (int idx = tid; idx < 256 * 32; idx += 256) {
        int row = idx >> 5, c = idx & 31;
        cpa(smaddr(&Bs[row * LS_KS + c * 8]), &Wh[(size_t)(n0 + row) * H_ + c * 8], 16);
    }
    cpa_wait();
    __syncthreads();

    float c_reg[2][8][2] = {};

    for (int t = 0; t < tlen; ++t) {
        const int t_idx = dir ? (tlen - 1 - t) : t;

        uint32_t xw_reg[2][8][2];
        #pragma unroll
        for (int i = 0; i < 2; ++i)
            #pragma unroll
            for (int j = 0; j < 8; ++j)
                #pragma unroll
                for (int half = 0; half < 2; ++half) {
                    int m = m0 + wm * 32 + i * 16 + g + half * 8;
                    int n = n0 + wn * 64 + j * 8 + 2 * tq;
                    size_t base = ((size_t)m * TMAIN + t_idx) * (size_t)G_;
                    xw_reg[i][j][half] = *(const uint32_t*)&xw[base + n];
                }

        float acc[2][8][4] = {};

        if (t > 0) {
            const bf16* __restrict__ hr =
                (MODE == 0) ? g_h16[dir][t & 1] : g_dh16[dir][t & 1];
            for (int idx = tid; idx < 64 * 32; idx += 256) {
                int row = idx >> 5, c = idx & 31;
                cpa(smaddr(&As[row * LS_KS + c * 8]), &hr[(size_t)(m0 + row) * H_ + c * 8], 16);
            }
            cpa_wait();
            __syncthreads();

            #pragma unroll
            for (int kk = 0; kk < H_ / 16; ++kk) {
                const int ko = kk * 16;
                uint32_t a[2][4], b[8][2];
                #pragma unroll
                for (int i = 0; i < 2; ++i) {
                    int ar = wm * 32 + i * 16;
                    a[i][0] = *(const uint32_t*)&As[(ar + g) * LS_KS + ko + 2 * tq];
                    a[i][1] = *(const uint32_t*)&As[(ar + g + 8) * LS_KS + ko + 2 * tq];
                    a[i][2] = *(const uint32_t*)&As[(ar + g) * LS_KS + ko + 2 * tq + 8];
                    a[i][3] = *(const uint32_t*)&As[(ar + g + 8) * LS_KS + ko + 2 * tq + 8];
                }
                #pragma unroll
                for (int j = 0; j < 8; ++j) {
                    int br = wn * 64 + j * 8 + g;
                    b[j][0] = *(const uint32_t*)&Bs[br * LS_KS + ko + 2 * tq];
                    b[j][1] = *(const uint32_t*)&Bs[br * LS_KS + ko + 2 * tq + 8];
                }
                #pragma unroll
                for (int i = 0; i < 2; ++i)
                    #pragma unroll
                    for (int j = 0; j < 8; ++j) mma16816(acc[i][j], a[i], b[j]);
            }
        }

        bf16* __restrict__ hw =
            (MODE == 0) ? g_h16[dir][(t & 1) ^ 1] : g_dh16[dir][(t & 1) ^ 1];

        #pragma unroll
        for (int i = 0; i < 2; ++i) {
            #pragma unroll
            for (int j = 0; j < 8; ++j) {
                #pragma unroll
                for (int half = 0; half < 2; ++half) {
                    int m = m0 + wm * 32 + i * 16 + g + half * 8;
                    int n = n0 + wn * 64 + j * 8 + 2 * tq;
                    __nv_bfloat162 xv = *(__nv_bfloat162*)&xw_reg[i][j][half];
                    float gv0 = acc[i][j][half * 2 + 0] + __bfloat162float(xv.x);
                    float gv1 = acc[i][j][half * 2 + 1] + __bfloat162float(xv.y);
                    float p0 = __shfl_xor_sync(0xffffffffu, gv0, 1);
                    float p1 = __shfl_xor_sync(0xffffffffu, gv1, 1);
                    if ((tq & 1) == 0) {
                        int u = n >> 2;
                        float c_old = (t > 0) ? c_reg[i][j][half] : 0.0f;
                        float ig = sigm(gv0), fg = sigm(gv1);
                        float gg = tanhf(p0), og = sigm(p1);
                        float c = fg * c_old + ig * gg;
                        float h = og * tanhf(c);
                        c_reg[i][j][half] = c;
                        hw[(size_t)m * H_ + u] = __float2bfloat16(h);
                        if (MODE == 0) {
                            if (t == tlen - 1) hf[(size_t)m * H_ + u] = h;
                        } else {
                            int pos = dir ? (S_ - 1 - t) : t;
                            docs[((size_t)m * S_ + pos) * H_ + u] = h;
                        }
                    }
                }
            }
        }

        if (t < tlen - 1) { CLUSTER_ARRIVE(); CLUSTER_WAIT(); }
    }
}

// ---------------- SourceBias (per-row, R10 version) ----------------
__global__ __launch_bounds__(256) void source_bias(
    const float* __restrict__ trans, const float* __restrict__ sbias,
    const int* __restrict__ urls) {
    const int row = blockIdx.x;
    const int tid = threadIdx.x;
    const int u = urls[row];

    __shared__ float xs[SEN2_];
    xs[tid]       = g_hf[0][(size_t)row * H_ + tid];
    xs[tid + H_]  = g_hf[1][(size_t)row * H_ + tid];
    __syncthreads();

    const int e0 = tid, e1 = tid + 256;
    float a0 = sbias[(size_t)u * SEN2_ + e0];
    float a1 = sbias[(size_t)u * SEN2_ + e1];
    const float* tp = trans + (size_t)u * SEN2_ * SEN2_;
    #pragma unroll 8
    for (int d = 0; d < SEN2_; ++d) {
        float x = xs[d];
        a0 += x * tp[(size_t)d * SEN2_ + e0];
        a1 += x * tp[(size_t)d * SEN2_ + e1];
    }
    g_biased16[(size_t)row * SEN2_ + e0] = __float2bfloat16(tanhf(a0));
    g_biased16[(size_t)row * SEN2_ + e1] = __float2bfloat16(tanhf(a1));
}

// ---------------- attention + heads ----------------
__device__ __forceinline__ float doc_elem(int b, int s, int d) {
    return (d < H_) ? g_docs[0][((size_t)b * S_ + s) * H_ + d]
                    : g_docs[1][((size_t)b * S_ + s) * H_ + d - H_];
}

__global__ __launch_bounds__(256) void attn_heads(
    const float* __restrict__ attn_W, const float* __restrict__ attn_b,
    const float* __restrict__ bW1, const float* __restrict__ bb1,
    const float* __restrict__ bW2, const float* __restrict__ bb2,
    const float* __restrict__ tW1, const float* __restrict__ tb1,
    const float* __restrict__ tW2, const float* __restrict__ tb2,
    float* __restrict__ out) {
    const int b = blockIdx.x;
    const int tid = threadIdx.x;

    __shared__ __align__(16) float head[SEN2_];
    __shared__ __align__(16) float v[SEN2_];
    __shared__ __align__(16) float rep[SEN2_];
    __shared__ float h1[H_];
    __shared__ float t1[H_];
    __shared__ float red[256];
    __shared__ float sc[S_];
    __shared__ float p5[5];

    head[tid]       = g_hf[0][(size_t)(NSEN_ + b) * H_ + tid];
    head[tid + H_]  = g_hf[1][(size_t)(NSEN_ + b) * H_ + tid];
    __syncthreads();

    #pragma unroll
    for (int q = 0; q < 2; ++q) {
        int d = tid + q * 256;
        const float4* wr = reinterpret_cast<const float4*>(attn_W + (size_t)d * SEN2_);
        const float4* hh = reinterpret_cast<const float4*>(head);
        float a = 0.0f;
        #pragma unroll 4
        for (int i = 0; i < SEN2_ / 4; ++i) {
            float4 w4 = wr[i], h4 = hh[i];
            a += w4.x * h4.x + w4.y * h4.y + w4.z * h4.z + w4.w * h4.w;
        }
        v[d] = a;
    }
    __syncthreads();

    for (int s = 0; s < S_; ++s) {
        float p = 0.0f;
        for (int d = tid; d < SEN2_; d += 256) p += doc_elem(b, s, d) * v[d];
        red[tid] = p;
        __syncthreads();
        for (int off = 128; off > 0; off >>= 1) {
            if (tid < off) red[tid] += red[tid + off];
            __syncthreads();
        }
        if (tid == 0) sc[s] = red[0] + attn_b[0];
        __syncthreads();
    }
    if (tid == 0) {
        float m = sc[0];
        for (int s = 1; s < S_; ++s) m = fmaxf(m, sc[s]);
        float sum = 0.0f;
        for (int s = 0; s < S_; ++s) { sc[s] = expf(sc[s] - m); sum += sc[s]; }
        float inv = 1.0f / sum;
        for (int s = 0; s < S_; ++s) sc[s] *= inv;
    }
    __syncthreads();

    #pragma unroll
    for (int q = 0; q < 2; ++q) {
        int d = tid + q * 256;
        float a = 0.0f;
        #pragma unroll
        for (int s = 0; s < S_; ++s) a += sc[s] * doc_elem(b, s, d);
        rep[d] = a;
    }
    __syncthreads();

    {
        const float4* rp = reinterpret_cast<const float4*>(rep);
        const float4* w1 = reinterpret_cast<const float4*>(bW1 + (size_t)tid * SEN2_);
        const float4* w2 = reinterpret_cast<const float4*>(tW1 + (size_t)tid * SEN2_);
        float a = bb1[tid], c = tb1[tid];
        #pragma unroll 4
        for (int i = 0; i < SEN2_ / 4; ++i) {
            float4 r4 = rp[i];
            float4 a4 = w1[i];
            float4 c4 = w2[i];
            a += a4.x * r4.x + a4.y * r4.y + a4.z * r4.z + a4.w * r4.w;
            c += c4.x * r4.x + c4.y * r4.y + c4.z * r4.z + c4.w * r4.w;
        }
        h1[tid] = tanhf(a);
        t1[tid] = tanhf(c);
    }
    __syncthreads();

    if (tid < 5) {
        float a = bb2[tid];
        const float* w = bW2 + (size_t)tid * H_;
        for (int j = 0; j < H_; ++j) a += h1[j] * w[j];
        p5[tid] = tanhf(a);
    }
    __syncthreads();
    if (tid == 0) {
        float m = p5[0];
        for (int k = 1; k < 5; ++k) m = fmaxf(m, p5[k]);
        float sum = 0.0f;
        float e[5];
        for (int k = 0; k < 5; ++k) { e[k] = expf(p5[k] - m); sum += e[k]; }
        float inv = 1.0f / sum;
        for (int k = 0; k < 5; ++k) out[(size_t)b * 5 + k] = e[k] * inv;

        float a = tb2[0];
        for (int j = 0; j < H_; ++j) a += t1[j] * tW2[j];
        out[B_ * 5 + b] = sigm(tanhf(a));
    }
}

// ---------------- launch ----------------
extern "C" void kernel_launch(void* const* d_in, const int* in_sizes, int n_in,
                              void* d_out, int out_size) {
    const int*   input_ids = (const int*)d_in[0];
    const int*   urls      = (const int*)d_in[1];
    const int*   titles    = (const int*)d_in[2];
    const float* emb       = (const float*)d_in[3];
    const float* sen_wih_f = (const float*)d_in[4];
    const float* sen_whh_f = (const float*)d_in[5];
    const float* sen_b_f   = (const float*)d_in[6];
    const float* sen_wih_b = (const float*)d_in[7];
    const float* sen_whh_b = (const float*)d_in[8];
    const float* sen_b_b   = (const float*)d_in[9];
    const float* trans     = (const float*)d_in[10];
    const float* sb_bias   = (const float*)d_in[11];
    const float* doc_wih_f = (const float*)d_in[12];
    const float* doc_whh_f = (const float*)d_in[13];
    const float* doc_b_f   = (const float*)d_in[14];
    const float* doc_wih_b = (const float*)d_in[15];
    const float* doc_whh_b = (const float*)d_in[16];
    const float* doc_b_b   = (const float*)d_in[17];
    const float* attn_W    = (const float*)d_in[18];
    const float* attn_b    = (const float*)d_in[19];
    const float* bias_W1   = (const float*)d_in[20];
    const float* bias_b1   = (const float*)d_in[21];
    const float* bias_W2   = (const float*)d_in[22];
    const float* bias_b2   = (const float*)d_in[23];
    const float* truth_W1  = (const float*)d_in[24];
    const float* truth_b1  = (const float*)d_in[25];
    const float* truth_W2  = (const float*)d_in[26];
    const float* truth_b2  = (const float*)d_in[27];
    float* out = (float*)d_out;

    static bool attr_done = false;
    if (!attr_done) {
        cudaFuncSetAttribute(proj_sen16, cudaFuncAttributeMaxDynamicSharedMemorySize, GP_BYTES);
        cudaFuncSetAttribute(proj_doc16, cudaFuncAttributeMaxDynamicSharedMemorySize, PDP_BYTES);
        cudaFuncSetAttribute(lstm_cluster<0>, cudaFuncAttributeMaxDynamicSharedMemorySize, LS_BYTES);
        cudaFuncSetAttribute(lstm_cluster<1>, cudaFuncAttributeMaxDynamicSharedMemorySize, LS_BYTES);
        attr_done = true;
    }

    gather_tokens<<<(MPROJ_ * (KP_ / 8) + 255) / 256, 256>>>(emb, input_ids, titles);
    conv_sen<<<(2 * G_ * KP_ + 2 * G_ * H_ + 2 * G_ + 255) / 256, 256>>>(
        sen_wih_f, sen_b_f, sen_wih_b, sen_b_b, sen_whh_f, sen_whh_b);
    conv_doc<<<(2 * G_ * SEN2_ + 2 * G_ * H_ + 2 * G_ + 255) / 256, 256>>>(
        doc_wih_f, doc_b_f, doc_wih_b, doc_b_b, doc_whh_f, doc_whh_b);

    proj_sen16<<<dim3(G_ / 128, MPROJ_ / 128, 2), 256, GP_BYTES>>>();

    lstm_cluster<0><<<dim3(4, NR_ / 64, 2), 256, LS_BYTES>>>();

    source_bias<<<NSEN_, 256>>>(trans, sb_bias, urls);

    proj_doc16<<<dim3(G_ / 128, NSEN_ / 64, 2), 256, PDP_BYTES>>>();

    lstm_cluster<1><<<dim3(4, 1, 2), 256, LS_BYTES>>>();

    attn_heads<<<B_, 256>>>(attn_W, attn_b, bias_W1, bias_b1, bias_W2, bias_b2,
                            truth_W1, truth_b1, truth_W2, truth_b2, out);
}

// round 15
// speedup vs baseline: 1.5047x; 1.5047x over previous
#include <cuda_runtime.h>
#include <cuda_bf16.h>
#include <math.h>
#include <stdint.h>

// ---------------- constants ----------------
#define B_ 64
#define S_ 10
#define L_ 30
#define TL_ 15
#define E_ 300
#define KP_ 320          // token-emb K padded to 320 (5 chunks of 64)
#define H_ 256
#define G_ 1024
#define SEN2_ 512
#define NSEN_ 640
#define NR_ 704
#define MPROJ_ (NR_*L_)
#define VOCAB_ 50000

#define LS_KS 264
#define LS_BYTES ((64 + 256) * LS_KS * 2)

// pipelined proj_sen: 128x128 tile, K-chunk 64, stride 72, 2 stages
#define GP_ST 72
#define GP_STAGE (2 * 128 * GP_ST)
#define GP_BYTES (2 * GP_STAGE * 2)

// pipelined proj_doc: 64x128 tile, K-chunk 64, stride 72, 2 stages
#define PDP_ST 72
#define PDP_STAGE ((64 + 128) * PDP_ST)
#define PDP_BYTES (2 * PDP_STAGE * 2)

typedef __nv_bfloat16 bf16;

// ---------------- scratch ----------------
__device__ bf16  g_A[MPROJ_ * KP_];
__device__ bf16  g_wih_s[2][G_*KP_];
__device__ bf16  g_whh_s[2][G_*H_];
__device__ float g_bias_s[2][G_];
__device__ bf16  g_wih_d[2][G_*SEN2_];
__device__ bf16  g_whh_d[2][G_*H_];
__device__ float g_bias_d[2][G_];
__device__ bf16  g_xw[2][MPROJ_*G_];
__device__ bf16  g_dxw[2][NSEN_*G_];
__device__ bf16  g_h16[2][2][NR_*H_];
__device__ float g_hf[2][NR_*H_];
__device__ bf16  g_dh16[2][2][B_*H_];
__device__ float g_docs[2][B_*S_*H_];
__device__ bf16  g_biased16[NSEN_*SEN2_];

__device__ __forceinline__ float sigm(float x) { return 1.0f / (1.0f + expf(-x)); }

// HW tanh (sm_75+): single-instruction, max rel err ~2^-11
__device__ __forceinline__ float tanh_fast(float x) {
    float y;
    asm("tanh.approx.f32 %0, %1;" : "=f"(y) : "f"(x));
    return y;
}
__device__ __forceinline__ float sigm_fast(float x) {
    return 0.5f * tanh_fast(0.5f * x) + 0.5f;
}

__device__ __forceinline__ void mma16816(float* d, const uint32_t* a, const uint32_t* b) {
    asm volatile(
        "mma.sync.aligned.m16n8k16.row.col.f32.bf16.bf16.f32 "
        "{%0,%1,%2,%3},{%4,%5,%6,%7},{%8,%9},{%0,%1,%2,%3};\n"
        : "+f"(d[0]), "+f"(d[1]), "+f"(d[2]), "+f"(d[3])
        : "r"(a[0]), "r"(a[1]), "r"(a[2]), "r"(a[3]), "r"(b[0]), "r"(b[1]));
}

__device__ __forceinline__ uint32_t smaddr(const void* p) {
    return (uint32_t)__cvta_generic_to_shared(p);
}
__device__ __forceinline__ void cpa(uint32_t d, const void* s, int sz) {
    asm volatile("cp.async.cg.shared.global [%0], [%1], 16, %2;\n"
                 :: "r"(d), "l"(s), "r"(sz));
}
__device__ __forceinline__ void cpa_commit() {
    asm volatile("cp.async.commit_group;\n" ::);
}
template <int N>
__device__ __forceinline__ void cpa_waitg() {
    asm volatile("cp.async.wait_group %0;\n" :: "n"(N));
}
__device__ __forceinline__ void cpa_wait() {
    asm volatile("cp.async.commit_group;\ncp.async.wait_group 0;\n" ::);
}

#define CLUSTER_ARRIVE() asm volatile("barrier.cluster.arrive.aligned;" ::: "memory")
#define CLUSTER_WAIT()   asm volatile("barrier.cluster.wait.aligned;" ::: "memory")

__device__ __forceinline__ uint32_t pack_bf2(float x, float y) {
    __nv_bfloat162 p = __floats2bfloat162_rn(x, y);
    return *(uint32_t*)&p;
}

// ---------------- token gather ----------------
__global__ void gather_tokens(const float* __restrict__ emb,
                              const int* __restrict__ ids,
                              const int* __restrict__ titles) {
    int idx = blockIdx.x * blockDim.x + threadIdx.x;
    const int total = MPROJ_ * (KP_ / 8);
    if (idx >= total) return;
    int m = idx / (KP_ / 8), cc = idx % (KP_ / 8);
    int r = m / L_, t = m - r * L_;
    int id;
    if (r < NSEN_) id = ids[r * L_ + t];
    else           id = (t < TL_) ? titles[(r - NSEN_) * TL_ + t] : -1;
    bf16 v[8];
    #pragma unroll
    for (int j = 0; j < 8; ++j) {
        int k = cc * 8 + j;
        float f = (id >= 0 && k < E_) ? emb[(size_t)id * E_ + k] : 0.0f;
        v[j] = __float2bfloat16(f);
    }
    *(uint4*)&g_A[(size_t)m * KP_ + cc * 8] = *(const uint4*)v;
}

// ---------------- weight conversion ----------------
__global__ void conv_sen(const float* __restrict__ wf, const float* __restrict__ bfp,
                         const float* __restrict__ wb, const float* __restrict__ bbp,
                         const float* __restrict__ whf, const float* __restrict__ whb) {
    int idx = blockIdx.x * blockDim.x + threadIdx.x;
    const int T1 = 2 * G_ * KP_;
    const int T2 = 2 * G_ * H_;
    if (idx < T1) {
        int dir = idx / (G_ * KP_);
        int r = (idx / KP_) % G_, k = idx % KP_;
        int u = r >> 2, gate = r & 3, src = gate * H_ + u;
        const float* W = dir ? wb : wf;
        g_wih_s[dir][r * KP_ + k] = __float2bfloat16(k < E_ ? W[(size_t)src * E_ + k] : 0.0f);
    } else if (idx < T1 + T2) {
        int j = idx - T1;
        int dir = j / (G_ * H_);
        int r = (j / H_) % G_, k = j % H_;
        int u = r >> 2, gate = r & 3, src = gate * H_ + u;
        const float* W = dir ? whb : whf;
        g_whh_s[dir][r * H_ + k] = __float2bfloat16(W[(size_t)src * H_ + k]);
    } else if (idx < T1 + T2 + 2 * G_) {
        int j = idx - T1 - T2;
        int dir = j / G_, r = j % G_;
        int u = r >> 2, gate = r & 3;
        g_bias_s[dir][r] = (dir ? bbp : bfp)[gate * H_ + u];
    }
}

__global__ void conv_doc(const float* __restrict__ wf, const float* __restrict__ bfp,
                         const float* __restrict__ wb, const float* __restrict__ bbp,
                         const float* __restrict__ whf, const float* __restrict__ whb) {
    int idx = blockIdx.x * blockDim.x + threadIdx.x;
    const int T1 = 2 * G_ * SEN2_;
    const int T2 = 2 * G_ * H_;
    if (idx < T1) {
        int dir = idx / (G_ * SEN2_);
        int r = (idx / SEN2_) % G_, k = idx % SEN2_;
        int u = r >> 2, gate = r & 3, src = gate * H_ + u;
        const float* W = dir ? wb : wf;
        g_wih_d[dir][r * SEN2_ + k] = __float2bfloat16(W[(size_t)src * SEN2_ + k]);
    } else if (idx < T1 + T2) {
        int j = idx - T1;
        int dir = j / (G_ * H_);
        int r = (j / H_) % G_, k = j % H_;
        int u = r >> 2, gate = r & 3, src = gate * H_ + u;
        const float* W = dir ? whb : whf;
        g_whh_d[dir][r * H_ + k] = __float2bfloat16(W[(size_t)src * H_ + k]);
    } else if (idx < T1 + T2 + 2 * G_) {
        int j = idx - T1 - T2;
        int dir = j / G_, r = j % G_;
        int u = r >> 2, gate = r & 3;
        g_bias_d[dir][r] = (dir ? bbp : bfp)[gate * H_ + u];
    }
}

// ---------------- sentence/title input projection ----------------
__global__ __launch_bounds__(256, 2) void proj_sen16() {
    extern __shared__ bf16 sm[];

    const int dir = blockIdx.z;
    const bf16* __restrict__ W = g_wih_s[dir];
    const float* __restrict__ bias = g_bias_s[dir];
    bf16* __restrict__ out = g_xw[dir];

    const int m0 = blockIdx.y * 128;
    const int n0 = blockIdx.x * 128;
    const int tid = threadIdx.x, lane = tid & 31, warp = tid >> 5;
    const int wm = warp >> 2, wn = warp & 3;
    const int g = lane >> 2, tq = lane & 3;

    auto load_chunk = [&](int c) {
        bf16* As_ = sm + (c & 1) * GP_STAGE;
        bf16* Bs_ = As_ + 128 * GP_ST;
        #pragma unroll
        for (int p = 0; p < 4; ++p) {
            int idx = tid + p * 256;
            int row = idx >> 3, cc = idx & 7;
            cpa(smaddr(&As_[row * GP_ST + cc * 8]),
                &g_A[(size_t)(m0 + row) * KP_ + c * 64 + cc * 8], 16);
            cpa(smaddr(&Bs_[row * GP_ST + cc * 8]),
                &W[(size_t)(n0 + row) * KP_ + c * 64 + cc * 8], 16);
        }
        cpa_commit();
    };

    float acc[4][4][4] = {};

    load_chunk(0);
    #pragma unroll 1
    for (int c = 0; c < KP_ / 64; ++c) {
        if (c + 1 < KP_ / 64) { load_chunk(c + 1); cpa_waitg<1>(); }
        else                  { cpa_waitg<0>(); }
        __syncthreads();

        const bf16* As_ = sm + (c & 1) * GP_STAGE;
        const bf16* Bs_ = As_ + 128 * GP_ST;
        #pragma unroll
        for (int kk = 0; kk < 4; ++kk) {
            const int ko = kk * 16;
            uint32_t a[4][4], b[4][2];
            #pragma unroll
            for (int i = 0; i < 4; ++i) {
                int ar = wm * 64 + i * 16;
                a[i][0] = *(const uint32_t*)&As_[(ar + g) * GP_ST + ko + 2 * tq];
                a[i][1] = *(const uint32_t*)&As_[(ar + g + 8) * GP_ST + ko + 2 * tq];
                a[i][2] = *(const uint32_t*)&As_[(ar + g) * GP_ST + ko + 2 * tq + 8];
                a[i][3] = *(const uint32_t*)&As_[(ar + g + 8) * GP_ST + ko + 2 * tq + 8];
            }
            #pragma unroll
            for (int j = 0; j < 4; ++j) {
                int br = wn * 32 + j * 8 + g;
                b[j][0] = *(const uint32_t*)&Bs_[br * GP_ST + ko + 2 * tq];
                b[j][1] = *(const uint32_t*)&Bs_[br * GP_ST + ko + 2 * tq + 8];
            }
            #pragma unroll
            for (int i = 0; i < 4; ++i)
                #pragma unroll
                for (int j = 0; j < 4; ++j) mma16816(acc[i][j], a[i], b[j]);
        }
        __syncthreads();
    }

    #pragma unroll
    for (int i = 0; i < 4; ++i) {
        #pragma unroll
        for (int j = 0; j < 4; ++j) {
            int mr = wm * 64 + i * 16 + g;
            int n = n0 + wn * 32 + j * 8 + 2 * tq;
            size_t o = (size_t)(m0 + mr) * G_ + n;
            *(uint32_t*)&out[o] =
                pack_bf2(acc[i][j][0] + bias[n], acc[i][j][1] + bias[n + 1]);
            o = (size_t)(m0 + mr + 8) * G_ + n;
            *(uint32_t*)&out[o] =
                pack_bf2(acc[i][j][2] + bias[n], acc[i][j][3] + bias[n + 1]);
        }
    }
}

// ---------------- document input projection (2-stage pipelined) ----------------
__global__ __launch_bounds__(256, 2) void proj_doc16() {
    extern __shared__ bf16 sm[];

    const int dir = blockIdx.z;
    const bf16* __restrict__ W = g_wih_d[dir];
    const float* __restrict__ bias = g_bias_d[dir];
    bf16* __restrict__ out = g_dxw[dir];

    const int m0 = blockIdx.y * 64;
    const int n0 = blockIdx.x * 128;
    const int tid = threadIdx.x, lane = tid & 31, warp = tid >> 5;
    const int wm = warp >> 2, wn = warp & 3;
    const int g = lane >> 2, tq = lane & 3;

    auto load_chunk = [&](int c) {
        bf16* As_ = sm + (c & 1) * PDP_STAGE;
        bf16* Bs_ = As_ + 64 * PDP_ST;
        #pragma unroll
        for (int p = 0; p < 2; ++p) {
            int idx = tid + p * 256;
            int row = idx >> 3, cc = idx & 7;
            cpa(smaddr(&As_[row * PDP_ST + cc * 8]),
                &g_biased16[(size_t)(m0 + row) * SEN2_ + c * 64 + cc * 8], 16);
        }
        #pragma unroll
        for (int p = 0; p < 4; ++p) {
            int idx = tid + p * 256;
            int row = idx >> 3, cc = idx & 7;
            cpa(smaddr(&Bs_[row * PDP_ST + cc * 8]),
                &W[(size_t)(n0 + row) * SEN2_ + c * 64 + cc * 8], 16);
        }
        cpa_commit();
    };

    float acc[2][4][4] = {};

    load_chunk(0);
    #pragma unroll 1
    for (int c = 0; c < SEN2_ / 64; ++c) {
        if (c + 1 < SEN2_ / 64) { load_chunk(c + 1); cpa_waitg<1>(); }
        else                    { cpa_waitg<0>(); }
        __syncthreads();

        const bf16* As_ = sm + (c & 1) * PDP_STAGE;
        const bf16* Bs_ = As_ + 64 * PDP_ST;
        #pragma unroll
        for (int kk = 0; kk < 4; ++kk) {
            const int ko = kk * 16;
            uint32_t a[2][4], b[4][2];
            #pragma unroll
            for (int i = 0; i < 2; ++i) {
                int ar = wm * 32 + i * 16;
                a[i][0] = *(const uint32_t*)&As_[(ar + g) * PDP_ST + ko + 2 * tq];
                a[i][1] = *(const uint32_t*)&As_[(ar + g + 8) * PDP_ST + ko + 2 * tq];
                a[i][2] = *(const uint32_t*)&As_[(ar + g) * PDP_ST + ko + 2 * tq + 8];
                a[i][3] = *(const uint32_t*)&As_[(ar + g + 8) * PDP_ST + ko + 2 * tq + 8];
            }
            #pragma unroll
            for (int j = 0; j < 4; ++j) {
                int br = wn * 32 + j * 8 + g;
                b[j][0] = *(const uint32_t*)&Bs_[br * PDP_ST + ko + 2 * tq];
                b[j][1] = *(const uint32_t*)&Bs_[br * PDP_ST + ko + 2 * tq + 8];
            }
            #pragma unroll
            for (int i = 0; i < 2; ++i)
                #pragma unroll
                for (int j = 0; j < 4; ++j) mma16816(acc[i][j], a[i], b[j]);
        }
        __syncthreads();
    }

    #pragma unroll
    for (int i = 0; i < 2; ++i) {
        #pragma unroll
        for (int j = 0; j < 4; ++j) {
            int mr = wm * 32 + i * 16 + g;
            int n = n0 + wn * 32 + j * 8 + 2 * tq;
            size_t o = (size_t)(m0 + mr) * G_ + n;
            *(uint32_t*)&out[o] =
                pack_bf2(acc[i][j][0] + bias[n], acc[i][j][1] + bias[n + 1]);
            o = (size_t)(m0 + mr + 8) * G_ + n;
            *(uint32_t*)&out[o] =
                pack_bf2(acc[i][j][2] + bias[n], acc[i][j][3] + bias[n + 1]);
        }
    }
}

// ---------------- cluster-persistent LSTM (fast nonlinearities) ----------------
template <int MODE>
__global__ __launch_bounds__(256, 1) __cluster_dims__(4, 1, 1)
void lstm_cluster() {
    extern __shared__ bf16 sm[];
    bf16* Bs = sm;
    bf16* As = sm + 256 * LS_KS;

    const int dir = blockIdx.z;
    const bf16* __restrict__ Wh = (MODE == 0) ? g_whh_s[dir] : g_whh_d[dir];
    const bf16* __restrict__ xw = (MODE == 0) ? g_xw[dir] : g_dxw[dir];
    float* __restrict__ hf = (MODE == 0) ? g_hf[dir] : nullptr;
    float* __restrict__ docs = (MODE == 1) ? g_docs[dir] : nullptr;

    const int m0 = blockIdx.y * 64;
    const int n0 = blockIdx.x * 256;
    const int tlen = (MODE == 0) ? ((m0 < NSEN_) ? L_ : TL_) : S_;
    const int TMAIN = (MODE == 0) ? L_ : S_;

    const int tid = threadIdx.x, lane = tid & 31, warp = tid >> 5;
    const int wm = warp >> 2, wn = warp & 3;
    const int g = lane >> 2, tq = lane & 3;

    for (int idx = tid; idx < 256 * 32; idx += 256) {
        int row = idx >> 5, c = idx & 31;
        cpa(smaddr(&Bs[row * LS_KS + c * 8]), &Wh[(size_t)(n0 + row) * H_ + c * 8], 16);
    }
    cpa_wait();
    __syncthreads();

    float c_reg[2][8][2] = {};

    for (int t = 0; t < tlen; ++t) {
        const int t_idx = dir ? (tlen - 1 - t) : t;

        uint32_t xw_reg[2][8][2];
        #pragma unroll
        for (int i = 0; i < 2; ++i)
            #pragma unroll
            for (int j = 0; j < 8; ++j)
                #pragma unroll
                for (int half = 0; half < 2; ++half) {
                    int m = m0 + wm * 32 + i * 16 + g + half * 8;
                    int n = n0 + wn * 64 + j * 8 + 2 * tq;
                    size_t base = ((size_t)m * TMAIN + t_idx) * (size_t)G_;
                    xw_reg[i][j][half] = *(const uint32_t*)&xw[base + n];
                }

        float acc[2][8][4] = {};

        if (t > 0) {
            const bf16* __restrict__ hr =
                (MODE == 0) ? g_h16[dir][t & 1] : g_dh16[dir][t & 1];
            for (int idx = tid; idx < 64 * 32; idx += 256) {
                int row = idx >> 5, c = idx & 31;
                cpa(smaddr(&As[row * LS_KS + c * 8]), &hr[(size_t)(m0 + row) * H_ + c * 8], 16);
            }
            cpa_wait();
            __syncthreads();

            #pragma unroll
            for (int kk = 0; kk < H_ / 16; ++kk) {
                const int ko = kk * 16;
                uint32_t a[2][4], b[8][2];
                #pragma unroll
                for (int i = 0; i < 2; ++i) {
                    int ar = wm * 32 + i * 16;
                    a[i][0] = *(const uint32_t*)&As[(ar + g) * LS_KS + ko + 2 * tq];
                    a[i][1] = *(const uint32_t*)&As[(ar + g + 8) * LS_KS + ko + 2 * tq];
                    a[i][2] = *(const uint32_t*)&As[(ar + g) * LS_KS + ko + 2 * tq + 8];
                    a[i][3] = *(const uint32_t*)&As[(ar + g + 8) * LS_KS + ko + 2 * tq + 8];
                }
                #pragma unroll
                for (int j = 0; j < 8; ++j) {
                    int br = wn * 64 + j * 8 + g;
                    b[j][0] = *(const uint32_t*)&Bs[br * LS_KS + ko + 2 * tq];
                    b[j][1] = *(const uint32_t*)&Bs[br * LS_KS + ko + 2 * tq + 8];
                }
                #pragma unroll
                for (int i = 0; i < 2; ++i)
                    #pragma unroll
                    for (int j = 0; j < 8; ++j) mma16816(acc[i][j], a[i], b[j]);
            }
        }

        bf16* __restrict__ hw =
            (MODE == 0) ? g_h16[dir][(t & 1) ^ 1] : g_dh16[dir][(t & 1) ^ 1];

        #pragma unroll
        for (int i = 0; i < 2; ++i) {
            #pragma unroll
            for (int j = 0; j < 8; ++j) {
                #pragma unroll
                for (int half = 0; half < 2; ++half) {
                    int m = m0 + wm * 32 + i * 16 + g + half * 8;
                    int n = n0 + wn * 64 + j * 8 + 2 * tq;
                    __nv_bfloat162 xv = *(__nv_bfloat162*)&xw_reg[i][j][half];
                    float gv0 = acc[i][j][half * 2 + 0] + __bfloat162float(xv.x);
                    float gv1 = acc[i][j][half * 2 + 1] + __bfloat162float(xv.y);
                    float p0 = __shfl_xor_sync(0xffffffffu, gv0, 1);
                    float p1 = __shfl_xor_sync(0xffffffffu, gv1, 1);
                    if ((tq & 1) == 0) {
                        int u = n >> 2;
                        float c_old = (t > 0) ? c_reg[i][j][half] : 0.0f;
                        float ig = sigm_fast(gv0), fg = sigm_fast(gv1);
                        float gg = tanh_fast(p0), og = sigm_fast(p1);
                        float c = fg * c_old + ig * gg;
                        float h = og * tanh_fast(c);
                        c_reg[i][j][half] = c;
                        hw[(size_t)m * H_ + u] = __float2bfloat16(h);
                        if (MODE == 0) {
                            if (t == tlen - 1) hf[(size_t)m * H_ + u] = h;
                        } else {
                            int pos = dir ? (S_ - 1 - t) : t;
                            docs[((size_t)m * S_ + pos) * H_ + u] = h;
                        }
                    }
                }
            }
        }

        if (t < tlen - 1) { CLUSTER_ARRIVE(); CLUSTER_WAIT(); }
    }
}

// ---------------- SourceBias (per-row, fast tanh) ----------------
__global__ __launch_bounds__(256) void source_bias(
    const float* __restrict__ trans, const float* __restrict__ sbias,
    const int* __restrict__ urls) {
    const int row = blockIdx.x;
    const int tid = threadIdx.x;
    const int u = urls[row];

    __shared__ float xs[SEN2_];
    xs[tid]       = g_hf[0][(size_t)row * H_ + tid];
    xs[tid + H_]  = g_hf[1][(size_t)row * H_ + tid];
    __syncthreads();

    const int e0 = tid, e1 = tid + 256;
    float a0 = sbias[(size_t)u * SEN2_ + e0];
    float a1 = sbias[(size_t)u * SEN2_ + e1];
    const float* tp = trans + (size_t)u * SEN2_ * SEN2_;
    #pragma unroll 8
    for (int d = 0; d < SEN2_; ++d) {
        float x = xs[d];
        a0 += x * tp[(size_t)d * SEN2_ + e0];
        a1 += x * tp[(size_t)d * SEN2_ + e1];
    }
    g_biased16[(size_t)row * SEN2_ + e0] = __float2bfloat16(tanh_fast(a0));
    g_biased16[(size_t)row * SEN2_ + e1] = __float2bfloat16(tanh_fast(a1));
}

// ---------------- attention + heads ----------------
__device__ __forceinline__ float doc_elem(int b, int s, int d) {
    return (d < H_) ? g_docs[0][((size_t)b * S_ + s) * H_ + d]
                    : g_docs[1][((size_t)b * S_ + s) * H_ + d - H_];
}

__global__ __launch_bounds__(256) void attn_heads(
    const float* __restrict__ attn_W, const float* __restrict__ attn_b,
    const float* __restrict__ bW1, const float* __restrict__ bb1,
    const float* __restrict__ bW2, const float* __restrict__ bb2,
    const float* __restrict__ tW1, const float* __restrict__ tb1,
    const float* __restrict__ tW2, const float* __restrict__ tb2,
    float* __restrict__ out) {
    const int b = blockIdx.x;
    const int tid = threadIdx.x;

    __shared__ __align__(16) float head[SEN2_];
    __shared__ __align__(16) float v[SEN2_];
    __shared__ __align__(16) float rep[SEN2_];
    __shared__ float h1[H_];
    __shared__ float t1[H_];
    __shared__ float red[256];
    __shared__ float sc[S_];
    __shared__ float p5[5];

    head[tid]       = g_hf[0][(size_t)(NSEN_ + b) * H_ + tid];
    head[tid + H_]  = g_hf[1][(size_t)(NSEN_ + b) * H_ + tid];
    __syncthreads();

    #pragma unroll
    for (int q = 0; q < 2; ++q) {
        int d = tid + q * 256;
        const float4* wr = reinterpret_cast<const float4*>(attn_W + (size_t)d * SEN2_);
        const float4* hh = reinterpret_cast<const float4*>(head);
        float a = 0.0f;
        #pragma unroll 4
        for (int i = 0; i < SEN2_ / 4; ++i) {
            float4 w4 = wr[i], h4 = hh[i];
            a += w4.x * h4.x + w4.y * h4.y + w4.z * h4.z + w4.w * h4.w;
        }
        v[d] = a;
    }
    __syncthreads();

    for (int s = 0; s < S_; ++s) {
        float p = 0.0f;
        for (int d = tid; d < SEN2_; d += 256) p += doc_elem(b, s, d) * v[d];
        red[tid] = p;
        __syncthreads();
        for (int off = 128; off > 0; off >>= 1) {
            if (tid < off) red[tid] += red[tid + off];
            __syncthreads();
        }
        if (tid == 0) sc[s] = red[0] + attn_b[0];
        __syncthreads();
    }
    if (tid == 0) {
        float m = sc[0];
        for (int s = 1; s < S_; ++s) m = fmaxf(m, sc[s]);
        float sum = 0.0f;
        for (int s = 0; s < S_; ++s) { sc[s] = expf(sc[s] - m); sum += sc[s]; }
        float inv = 1.0f / sum;
        for (int s = 0; s < S_; ++s) sc[s] *= inv;
    }
    __syncthreads();

    #pragma unroll
    for (int q = 0; q < 2; ++q) {
        int d = tid + q * 256;
        float a = 0.0f;
        #pragma unroll
        for (int s = 0; s < S_; ++s) a += sc[s] * doc_elem(b, s, d);
        rep[d] = a;
    }
    __syncthreads();

    {
        const float4* rp = reinterpret_cast<const float4*>(rep);
        const float4* w1 = reinterpret_cast<const float4*>(bW1 + (size_t)tid * SEN2_);
        const float4* w2 = reinterpret_cast<const float4*>(tW1 + (size_t)tid * SEN2_);
        float a = bb1[tid], c = tb1[tid];
        #pragma unroll 4
        for (int i = 0; i < SEN2_ / 4; ++i) {
            float4 r4 = rp[i];
            float4 a4 = w1[i];
            float4 c4 = w2[i];
            a += a4.x * r4.x + a4.y * r4.y + a4.z * r4.z + a4.w * r4.w;
            c += c4.x * r4.x + c4.y * r4.y + c4.z * r4.z + c4.w * r4.w;
        }
        h1[tid] = tanh_fast(a);
        t1[tid] = tanh_fast(c);
    }
    __syncthreads();

    if (tid < 5) {
        float a = bb2[tid];
        const float* w = bW2 + (size_t)tid * H_;
        for (int j = 0; j < H_; ++j) a += h1[j] * w[j];
        p5[tid] = tanh_fast(a);
    }
    __syncthreads();
    if (tid == 0) {
        float m = p5[0];
        for (int k = 1; k < 5; ++k) m = fmaxf(m, p5[k]);
        float sum = 0.0f;
        float e[5];
        for (int k = 0; k < 5; ++k) { e[k] = expf(p5[k] - m); sum += e[k]; }
        float inv = 1.0f / sum;
        for (int k = 0; k < 5; ++k) out[(size_t)b * 5 + k] = e[k] * inv;

        float a = tb2[0];
        for (int j = 0; j < H_; ++j) a += t1[j] * tW2[j];
        out[B_ * 5 + b] = sigm(tanh_fast(a));
    }
}

// ---------------- launch ----------------
extern "C" void kernel_launch(void* const* d_in, const int* in_sizes, int n_in,
                              void* d_out, int out_size) {
    const int*   input_ids = (const int*)d_in[0];
    const int*   urls      = (const int*)d_in[1];
    const int*   titles    = (const int*)d_in[2];
    const float* emb       = (const float*)d_in[3];
    const float* sen_wih_f = (const float*)d_in[4];
    const float* sen_whh_f = (const float*)d_in[5];
    const float* sen_b_f   = (const float*)d_in[6];
    const float* sen_wih_b = (const float*)d_in[7];
    const float* sen_whh_b = (const float*)d_in[8];
    const float* sen_b_b   = (const float*)d_in[9];
    const float* trans     = (const float*)d_in[10];
    const float* sb_bias   = (const float*)d_in[11];
    const float* doc_wih_f = (const float*)d_in[12];
    const float* doc_whh_f = (const float*)d_in[13];
    const float* doc_b_f   = (const float*)d_in[14];
    const float* doc_wih_b = (const float*)d_in[15];
    const float* doc_whh_b = (const float*)d_in[16];
    const float* doc_b_b   = (const float*)d_in[17];
    const float* attn_W    = (const float*)d_in[18];
    const float* attn_b    = (const float*)d_in[19];
    const float* bias_W1   = (const float*)d_in[20];
    const float* bias_b1   = (const float*)d_in[21];
    const float* bias_W2   = (const float*)d_in[22];
    const float* bias_b2   = (const float*)d_in[23];
    const float* truth_W1  = (const float*)d_in[24];
    const float* truth_b1  = (const float*)d_in[25];
    const float* truth_W2  = (const float*)d_in[26];
    const float* truth_b2  = (const float*)d_in[27];
    float* out = (float*)d_out;

    static bool attr_done = false;
    if (!attr_done) {
        cudaFuncSetAttribute(proj_sen16, cudaFuncAttributeMaxDynamicSharedMemorySize, GP_BYTES);
        cudaFuncSetAttribute(proj_doc16, cudaFuncAttributeMaxDynamicSharedMemorySize, PDP_BYTES);
        cudaFuncSetAttribute(lstm_cluster<0>, cudaFuncAttributeMaxDynamicSharedMemorySize, LS_BYTES);
        cudaFuncSetAttribute(lstm_cluster<1>, cudaFuncAttributeMaxDynamicSharedMemorySize, LS_BYTES);
        attr_done = true;
    }

    gather_tokens<<<(MPROJ_ * (KP_ / 8) + 255) / 256, 256>>>(emb, input_ids, titles);
    conv_sen<<<(2 * G_ * KP_ + 2 * G_ * H_ + 2 * G_ + 255) / 256, 256>>>(
        sen_wih_f, sen_b_f, sen_wih_b, sen_b_b, sen_whh_f, sen_whh_b);
    conv_doc<<<(2 * G_ * SEN2_ + 2 * G_ * H_ + 2 * G_ + 255) / 256, 256>>>(
        doc_wih_f, doc_b_f, doc_wih_b, doc_b_b, doc_whh_f, doc_whh_b);

    proj_sen16<<<dim3(G_ / 128, MPROJ_ / 128, 2), 256, GP_BYTES>>>();

    lstm_cluster<0><<<dim3(4, NR_ / 64, 2), 256, LS_BYTES>>>();

    source_bias<<<NSEN_, 256>>>(trans, sb_bias, urls);

    proj_doc16<<<dim3(G_ / 128, NSEN_ / 64, 2), 256, PDP_BYTES>>>();

    lstm_cluster<1><<<dim3(4, 1, 2), 256, LS_BYTES>>>();

    attn_heads<<<B_, 256>>>(attn_W, attn_b, bias_W1, bias_b1, bias_W2, bias_b2,
                            truth_W1, truth_b1, truth_W2, truth_b2, out);
}